// round 2
// baseline (speedup 1.0000x reference)
#include <cuda_runtime.h>

#define FEPS 1e-12f

typedef unsigned long long u64;
struct pf { u64 u; };

// ---------- packed f32x2 primitives ----------
__device__ __forceinline__ pf pack2(float a, float b) {
    pf r; asm("mov.b64 %0, {%1, %2};" : "=l"(r.u) : "f"(a), "f"(b)); return r;
}
__device__ __forceinline__ void unpack2(pf a, float& x, float& y) {
    asm("mov.b64 {%0, %1}, %2;" : "=f"(x), "=f"(y) : "l"(a.u));
}
__device__ __forceinline__ pf bc(float c) {
    pf r; asm("mov.b64 %0, {%1, %1};" : "=l"(r.u) : "f"(c)); return r;
}
__device__ __forceinline__ pf padd(pf a, pf b) {
    pf r; asm("add.rn.f32x2 %0, %1, %2;" : "=l"(r.u) : "l"(a.u), "l"(b.u)); return r;
}
__device__ __forceinline__ pf pmul(pf a, pf b) {
    pf r; asm("mul.rn.f32x2 %0, %1, %2;" : "=l"(r.u) : "l"(a.u), "l"(b.u)); return r;
}
__device__ __forceinline__ pf pfma(pf a, pf b, pf c) {
    pf r; asm("fma.rn.f32x2 %0, %1, %2, %3;" : "=l"(r.u) : "l"(a.u), "l"(b.u), "l"(c.u)); return r;
}
__device__ __forceinline__ pf psub(pf a, pf b) {             // a - b = fma(b, -1, a)
    pf n1 = bc(-1.0f); return pfma(b, n1, a);
}

// ---------- per-lane MUFU ----------
__device__ __forceinline__ float ex2a(float x) { float r; asm("ex2.approx.f32 %0, %1;"   : "=f"(r) : "f"(x)); return r; }
__device__ __forceinline__ float rcpa(float x) { float r; asm("rcp.approx.f32 %0, %1;"   : "=f"(r) : "f"(x)); return r; }
__device__ __forceinline__ float rsqa(float x) { float r; asm("rsqrt.approx.f32 %0, %1;" : "=f"(r) : "f"(x)); return r; }
__device__ __forceinline__ float sina(float x) { float r; asm("sin.approx.f32 %0, %1;"   : "=f"(r) : "f"(x)); return r; }
__device__ __forceinline__ float cosa(float x) { float r; asm("cos.approx.f32 %0, %1;"   : "=f"(r) : "f"(x)); return r; }
__device__ __forceinline__ float frcp(float x) {             // approx + 1 NR step
    float r = rcpa(x); return r * (2.0f - x * r);
}

// ---------- weight bank: pre-duplicated f32x2 pairs ----------
#define OJw1 0
#define OJb1 40
#define OJw2 50
#define OJb2 110
#define OVw1 116
#define OVb1 156
#define OVg  166
#define Ogw1 206
#define Ogb1 246
#define Ogw2 256
#define Ogb2 286
#define NW   289

__constant__ u64 cW2[NW];
__device__   u64 gStage[NW];

__device__ __forceinline__ pf W(int i) { pf r; r.u = cW2[i]; return r; }

// gather all weights (with pre-folds) into staging as duplicated pairs
__global__ void setup_kernel(const float* Jw1, const float* Jb1, const float* Jw2, const float* Jb2,
                             const float* Vw1, const float* Vb1, const float* Vw2,
                             const float* gw1, const float* gb1, const float* gw2, const float* gb2) {
    int i = threadIdx.x;
    float v;
    if      (i < 40)  v = Jw1[i];
    else if (i < 50)  v = Jb1[i - 40];
    else if (i < 110) v = Jw2[i - 50];
    else if (i < 116) v = Jb2[i - 110];
    else if (i < 156) v = Vw1[i - 116];
    else if (i < 166) v = Vb1[i - 156];
    else if (i < 206) { int t = i - 166; v = 4.0f * Vw2[t >> 2] * Vw1[t]; }  // Vg[k][j]=4*Vw2[k]*Vw1[4k+j]
    else if (i < 246) v = gw1[i - 206];
    else if (i < 256) v = gb1[i - 246];
    else if (i < 286) v = gw2[i - 256];
    else if (i < NW)  v = gb2[i - 286];
    else return;
    unsigned int b = __float_as_uint(v);
    gStage[i] = ((u64)b << 32) | b;
}

// packed tanh: 1 - 2/(exp(2x)+1), ex2 + rcp per lane
__device__ __forceinline__ pf ptanh(pf z) {
    pf zz = pmul(z, bc(2.8853900817779268f));   // 2*log2(e)
    float a, b; unpack2(zz, a, b);
    float ea = ex2a(a), eb = ex2a(b);
    float ra = rcpa(ea + 1.0f), rb = rcpa(eb + 1.0f);
    pf r = pack2(ra, rb);
    return pfma(r, bc(-2.0f), bc(1.0f));
}

// packed dV/dq of the V MLP: d_j = sum_k Vg[k][j] * r_k*(1-r_k), r_k = 1/(exp(2z_k)+1)
__device__ __forceinline__ void vgrad2(pf q0, pf q1, pf q2, pf q3,
                                       pf& d0, pf& d1, pf& d2, pf& d3) {
    d0 = bc(0.0f); d1 = d0; d2 = d0; d3 = d0;
#pragma unroll
    for (int k = 0; k < 10; k++) {
        pf z = W(OVb1 + k);
        z = pfma(W(OVw1 + 4*k + 0), q0, z);
        z = pfma(W(OVw1 + 4*k + 1), q1, z);
        z = pfma(W(OVw1 + 4*k + 2), q2, z);
        z = pfma(W(OVw1 + 4*k + 3), q3, z);
        pf zz = pmul(z, bc(2.8853900817779268f));
        float a, b; unpack2(zz, a, b);
        float ra = rcpa(ex2a(a) + 1.0f), rb = rcpa(ex2a(b) + 1.0f);
        pf S = pack2(ra * (1.0f - ra), rb * (1.0f - rb));   // = (1-t^2)/4
        d0 = pfma(W(OVg + 4*k + 0), S, d0);
        d1 = pfma(W(OVg + 4*k + 1), S, d1);
        d2 = pfma(W(OVg + 4*k + 2), S, d2);
        d3 = pfma(W(OVg + 4*k + 3), S, d3);
    }
}

__global__ void __launch_bounds__(128)
step2_kernel(const float4* __restrict__ xin, float4* __restrict__ xout, int B2) {
    int i = blockIdx.x * 128 + threadIdx.x;
    if (i >= B2) return;

    float4 a0 = xin[4*i + 0], a1 = xin[4*i + 1];   // row A
    float4 b0 = xin[4*i + 2], b1 = xin[4*i + 3];   // row B

    pf q0 = pack2(a0.x, b0.x), q1 = pack2(a0.y, b0.y), q2 = pack2(a0.z, b0.z), q3 = pack2(a0.w, b0.w);
    pf w0 = pack2(a1.x, b1.x), w1 = pack2(a1.y, b1.y), w2 = pack2(a1.z, b1.z), uu = pack2(a1.w, b1.w);

    // ---- J MLP -> l[6] ----
    pf hd[10];
#pragma unroll
    for (int k = 0; k < 10; k++) {
        pf z = W(OJb1 + k);
        z = pfma(W(OJw1 + 4*k + 0), q0, z);
        z = pfma(W(OJw1 + 4*k + 1), q1, z);
        z = pfma(W(OJw1 + 4*k + 2), q2, z);
        z = pfma(W(OJw1 + 4*k + 3), q3, z);
        hd[k] = ptanh(z);
    }
    pf l[6];
#pragma unroll
    for (int r6 = 0; r6 < 6; r6++) {
        pf s = W(OJb2 + r6);
#pragma unroll
        for (int k = 0; k < 10; k++) s = pfma(W(OJw2 + 10*r6 + k), hd[k], s);
        l[r6] = s;
    }

    // ---- M = L L^T + 0.01 I ----
    pf M00 = pfma(l[0], l[0], bc(0.01f));
    pf M01 = pmul(l[0], l[1]);
    pf M02 = pmul(l[0], l[3]);
    pf M11 = pfma(l[2], l[2], pfma(l[1], l[1], bc(0.01f)));
    pf M12 = pfma(l[2], l[4], pmul(l[1], l[3]));
    pf M22 = pfma(l[5], l[5], pfma(l[4], l[4], pfma(l[3], l[3], bc(0.01f))));

    // ---- J = inv(M), adjugate + per-lane rcp(NR) ----
    pf c00 = psub(pmul(M11, M22), pmul(M12, M12));
    pf c01 = psub(pmul(M02, M12), pmul(M01, M22));
    pf c02 = psub(pmul(M01, M12), pmul(M02, M11));
    pf c11 = psub(pmul(M00, M22), pmul(M02, M02));
    pf c12 = psub(pmul(M01, M02), pmul(M00, M12));
    pf c22 = psub(pmul(M00, M11), pmul(M01, M01));
    pf det = pfma(M02, c02, pfma(M01, c01, pmul(M00, c00)));
    {
        float dA, dB; unpack2(det, dA, dB);
        det = pack2(frcp(dA), frcp(dB));
    }
    pf J00 = pmul(c00, det), J01 = pmul(c01, det), J02 = pmul(c02, det);
    pf J11 = pmul(c11, det), J12 = pmul(c12, det), J22 = pmul(c22, det);

    // ---- g MLP -> fk = (h/2)*u*g ----
    pf fk0, fk1, fk2;
    {
#pragma unroll
        for (int k = 0; k < 10; k++) {
            pf z = W(Ogb1 + k);
            z = pfma(W(Ogw1 + 4*k + 0), q0, z);
            z = pfma(W(Ogw1 + 4*k + 1), q1, z);
            z = pfma(W(Ogw1 + 4*k + 2), q2, z);
            z = pfma(W(Ogw1 + 4*k + 3), q3, z);
            hd[k] = ptanh(z);
        }
        pf g0 = W(Ogb2 + 0), g1 = W(Ogb2 + 1), g2 = W(Ogb2 + 2);
#pragma unroll
        for (int k = 0; k < 10; k++) {
            g0 = pfma(W(Ogw2 + k),      hd[k], g0);
            g1 = pfma(W(Ogw2 + 10 + k), hd[k], g1);
            g2 = pfma(W(Ogw2 + 20 + k), hd[k], g2);
        }
        pf cu = pmul(uu, bc(0.005f));    // h*u/2
        fk0 = pmul(cu, g0); fk1 = pmul(cu, g1); fk2 = pmul(cu, g2);
    }

    // ---- pk = 2 J w ----
    pf pk0 = pmul(bc(2.0f), pfma(J02, w2, pfma(J01, w1, pmul(J00, w0))));
    pf pk1 = pmul(bc(2.0f), pfma(J12, w2, pfma(J11, w1, pmul(J01, w0))));
    pf pk2 = pmul(bc(2.0f), pfma(J22, w2, pfma(J12, w1, pmul(J02, w0))));

    // ---- dV at qk, Hd = H(qk) dV ----
    pf dv0, dv1, dv2, dv3;
    vgrad2(q0, q1, q2, q3, dv0, dv1, dv2, dv3);
    pf Hd0 = pfma(q1, dv0, pfma(q0, dv1, psub(pmul(q3, dv2), pmul(q2, dv3))));
    pf Hd1 = pfma(q2, dv0, pfma(q0, dv2, psub(pmul(q1, dv3), pmul(q3, dv1))));
    pf Hd2 = pfma(q3, dv0, pfma(q0, dv3, psub(pmul(q2, dv1), pmul(q1, dv2))));

    // ---- NR = -RHS = h/4*(pk + fk - h/2*Hd) ----
    pf NR0 = pmul(bc(0.0025f), pfma(bc(-0.005f), Hd0, padd(pk0, fk0)));
    pf NR1 = pmul(bc(0.0025f), pfma(bc(-0.005f), Hd1, padd(pk1, fk1)));
    pf NR2 = pmul(bc(0.0025f), pfma(bc(-0.005f), Hd2, padd(pk2, fk2)));

    // ---- Newton, 4 iterations ----
    pf xi0 = bc(0.0f), xi1 = xi0, xi2 = xi0;
#pragma unroll
    for (int it = 0; it < 4; it++) {
        pf s2 = pfma(xi2, xi2, pfma(xi1, xi1, pmul(xi0, xi0)));
        float sA, sB; unpack2(s2, sA, sB);
        // per-lane scalar prep (EPS-gated exactly like JAX's max(s,EPS) grad)
        float sclA = fmaxf(sA, FEPS), sclB = fmaxf(sB, FEPS);
        float rsA = rsqa(sclA),       rsB = rsqa(sclB);
        float thA = sclA * rsA,       thB = sclB * rsB;
        float snA = sina(thA),        snB = sina(thB);
        float csA = cosa(thA),        csB = cosa(thB);
        float siA = snA * rsA,        siB = snB * rsB;          // sinc
        float gsA = (sA >= FEPS) ? rsA : 0.0f;
        float gsB = (sB >= FEPS) ? rsB : 0.0f;
        float bsA = (csA - siA) * rsA * gsA, bsB = (csB - siB) * rsB * gsB;
        float dsA = -snA * gsA,       dsB = -snB * gsB;
        float a1A = -csA * siA,       a1B = -csB * siB;         // cs*nsinc (also -cs*sinc)
        float n2A = -siA * siA,       n2B = -siB * siB;         // -sinc^2
        float alA = dsA * (-siA) - csA * bsA;
        float alB = dsB * (-siB) - csB * bsB;
        float gaA = -2.0f * siA * bsA, gaB = -2.0f * siB * bsB;
        pf A1 = pack2(a1A, a1B), NS2 = pack2(n2A, n2B);
        pf AL = pack2(alA, alB), GA  = pack2(gaA, gaB);

        pf Jx0 = pfma(J02, xi2, pfma(J01, xi1, pmul(J00, xi0)));
        pf Jx1 = pfma(J12, xi2, pfma(J11, xi1, pmul(J01, xi0)));
        pf Jx2 = pfma(J22, xi2, pfma(J12, xi1, pmul(J02, xi0)));
        pf cx0 = psub(pmul(xi1, Jx2), pmul(xi2, Jx1));
        pf cx1 = psub(pmul(xi2, Jx0), pmul(xi0, Jx2));
        pf cx2 = psub(pmul(xi0, Jx1), pmul(xi1, Jx0));

        // residual: r = cs*m - qv x m - RHS, with m = -sinc*Jx, qv = -sinc*xi
        pf r0 = pfma(A1, Jx0, pfma(NS2, cx0, NR0));
        pf r1 = pfma(A1, Jx1, pfma(NS2, cx1, NR1));
        pf r2 = pfma(A1, Jx2, pfma(NS2, cx2, NR2));

        pf w30 = pfma(GA, cx0, pmul(AL, Jx0));
        pf w31 = pfma(GA, cx1, pmul(AL, Jx1));
        pf w32 = pfma(GA, cx2, pmul(AL, Jx2));

        // xi x J columns
        pf xJ00 = psub(pmul(xi1, J02), pmul(xi2, J01));
        pf xJ01 = psub(pmul(xi2, J00), pmul(xi0, J02));
        pf xJ02 = psub(pmul(xi0, J01), pmul(xi1, J00));
        pf xJ10 = psub(pmul(xi1, J12), pmul(xi2, J11));
        pf xJ11 = psub(pmul(xi2, J01), pmul(xi0, J12));
        pf xJ12 = psub(pmul(xi0, J11), pmul(xi1, J01));
        pf xJ20 = psub(pmul(xi1, J22), pmul(xi2, J12));
        pf xJ21 = psub(pmul(xi2, J02), pmul(xi0, J22));
        pf xJ22 = psub(pmul(xi0, J12), pmul(xi1, J02));
        // T_k = e_k x Jx + xi x Jcol_k
        pf T00 = xJ00;            pf T01 = psub(xJ01, Jx2); pf T02 = padd(xJ02, Jx1);
        pf T10 = padd(xJ10, Jx2); pf T11 = xJ11;            pf T12 = psub(xJ12, Jx0);
        pf T20 = psub(xJ20, Jx1); pf T21 = padd(xJ21, Jx0); pf T22 = xJ22;

        // A[j][k] = xi_k*w3_j + A1*J[j][k] + NS2*T_k[j]
        pf A00 = pfma(xi0, w30, pfma(A1, J00, pmul(NS2, T00)));
        pf A10 = pfma(xi0, w31, pfma(A1, J01, pmul(NS2, T01)));
        pf A20 = pfma(xi0, w32, pfma(A1, J02, pmul(NS2, T02)));
        pf A01 = pfma(xi1, w30, pfma(A1, J01, pmul(NS2, T10)));
        pf A11 = pfma(xi1, w31, pfma(A1, J11, pmul(NS2, T11)));
        pf A21 = pfma(xi1, w32, pfma(A1, J12, pmul(NS2, T12)));
        pf A02 = pfma(xi2, w30, pfma(A1, J02, pmul(NS2, T20)));
        pf A12 = pfma(xi2, w31, pfma(A1, J12, pmul(NS2, T21)));
        pf A22 = pfma(xi2, w32, pfma(A1, J22, pmul(NS2, T22)));

        // Cramer solve A d = r
        pf cvt0 = psub(pmul(A11, A22), pmul(A21, A12));
        pf cvt1 = psub(pmul(A21, A02), pmul(A01, A22));
        pf cvt2 = psub(pmul(A01, A12), pmul(A11, A02));
        pf ctu0 = psub(pmul(A12, A20), pmul(A22, A10));
        pf ctu1 = psub(pmul(A22, A00), pmul(A02, A20));
        pf ctu2 = psub(pmul(A02, A10), pmul(A12, A00));
        pf cuv0 = psub(pmul(A10, A21), pmul(A20, A11));
        pf cuv1 = psub(pmul(A20, A01), pmul(A00, A21));
        pf cuv2 = psub(pmul(A00, A11), pmul(A10, A01));
        pf dt = pfma(A20, cvt2, pfma(A10, cvt1, pmul(A00, cvt0)));
        float dA, dB; unpack2(dt, dA, dB);
        pf NID = pack2(-frcp(dA), -frcp(dB));
        pf n0 = pfma(r2, cvt2, pfma(r1, cvt1, pmul(r0, cvt0)));
        pf n1 = pfma(r2, ctu2, pfma(r1, ctu1, pmul(r0, ctu0)));
        pf n2 = pfma(r2, cuv2, pfma(r1, cuv1, pmul(r0, cuv0)));
        xi0 = pfma(n0, NID, xi0);
        xi1 = pfma(n1, NID, xi1);
        xi2 = pfma(n2, NID, xi2);
    }

    // ---- e = quat_exp(xi) ----
    pf E0, SC;
    {
        pf s2 = pfma(xi2, xi2, pfma(xi1, xi1, pmul(xi0, xi0)));
        float sA, sB; unpack2(s2, sA, sB);
        float sclA = fmaxf(sA, FEPS), sclB = fmaxf(sB, FEPS);
        float rsA = rsqa(sclA),       rsB = rsqa(sclB);
        float thA = sclA * rsA,       thB = sclB * rsB;
        E0 = pack2(cosa(thA), cosa(thB));
        SC = pack2(sina(thA) * rsA, sina(thB) * rsB);
    }
    pf e1 = pmul(xi0, SC), e2 = pmul(xi1, SC), e3 = pmul(xi2, SC);

    // ---- qn = quat_mul(qk, e) ----
    pf qn0 = psub(pmul(q0, E0), pfma(q3, e3, pfma(q2, e2, pmul(q1, e1))));
    pf qn1 = pfma(q0, e1, pfma(q1, E0, psub(pmul(q2, e3), pmul(q3, e2))));
    pf qn2 = pfma(q0, e2, pfma(q2, E0, psub(pmul(q3, e1), pmul(q1, e3))));
    pf qn3 = pfma(q0, e3, pfma(q3, E0, psub(pmul(q1, e2), pmul(q2, e1))));

    // ---- dV at qn ----
    pf dn0, dn1, dn2, dn3;
    vgrad2(qn0, qn1, qn2, qn3, dn0, dn1, dn2, dn3);

    // ---- qq = quat_mul(conj(qk), qn) ----
    pf qq0 = pfma(q3, qn3, pfma(q2, qn2, pfma(q1, qn1, pmul(q0, qn0))));
    pf qq1 = pfma(q0, qn1, psub(psub(pmul(q3, qn2), pmul(q1, qn0)), pmul(q2, qn3)));
    pf qq2 = pfma(q0, qn2, psub(psub(pmul(q1, qn3), pmul(q2, qn0)), pmul(q3, qn1)));
    pf qq3 = pfma(q0, qn3, psub(psub(pmul(q2, qn1), pmul(q1, qn2)), pmul(q3, qn0)));

    // ---- y = J qq_v ; G = qq0*y - qq_v x y ----
    pf y0 = pfma(J02, qq3, pfma(J01, qq2, pmul(J00, qq1)));
    pf y1 = pfma(J12, qq3, pfma(J11, qq2, pmul(J01, qq1)));
    pf y2 = pfma(J22, qq3, pfma(J12, qq2, pmul(J02, qq1)));
    pf G0 = pfma(qq0, y0, psub(pmul(qq3, y1), pmul(qq2, y2)));
    pf G1 = pfma(qq0, y1, psub(pmul(qq1, y2), pmul(qq3, y0)));
    pf G2 = pfma(qq0, y2, psub(pmul(qq2, y0), pmul(qq1, y1)));

    // ---- Hn = H(qn) dn ----
    pf Hn0 = pfma(qn1, dn0, pfma(qn0, dn1, psub(pmul(qn3, dn2), pmul(qn2, dn3))));
    pf Hn1 = pfma(qn2, dn0, pfma(qn0, dn2, psub(pmul(qn1, dn3), pmul(qn3, dn1))));
    pf Hn2 = pfma(qn3, dn0, pfma(qn0, dn3, psub(pmul(qn2, dn1), pmul(qn1, dn2))));

    // ---- pn = 400*G - 0.005*Hn + fk ; wn = 0.5 M pn ----
    pf pn0 = pfma(bc(400.0f), G0, pfma(bc(-0.005f), Hn0, fk0));
    pf pn1 = pfma(bc(400.0f), G1, pfma(bc(-0.005f), Hn1, fk1));
    pf pn2 = pfma(bc(400.0f), G2, pfma(bc(-0.005f), Hn2, fk2));
    pf wn0 = pmul(bc(0.5f), pfma(M02, pn2, pfma(M01, pn1, pmul(M00, pn0))));
    pf wn1 = pmul(bc(0.5f), pfma(M12, pn2, pfma(M11, pn1, pmul(M01, pn0))));
    pf wn2 = pmul(bc(0.5f), pfma(M22, pn2, pfma(M12, pn1, pmul(M02, pn0))));

    // ---- store both rows ----
    float qa0, qb0, qa1, qb1, qa2, qb2, qa3, qb3;
    unpack2(qn0, qa0, qb0); unpack2(qn1, qa1, qb1);
    unpack2(qn2, qa2, qb2); unpack2(qn3, qa3, qb3);
    float wa0, wb0, wa1, wb1, wa2, wb2, ua, ub;
    unpack2(wn0, wa0, wb0); unpack2(wn1, wa1, wb1);
    unpack2(wn2, wa2, wb2); unpack2(uu, ua, ub);

    xout[4*i + 0] = make_float4(qa0, qa1, qa2, qa3);
    xout[4*i + 1] = make_float4(wa0, wa1, wa2, ua);
    xout[4*i + 2] = make_float4(qb0, qb1, qb2, qb3);
    xout[4*i + 3] = make_float4(wb0, wb1, wb2, ub);
}

extern "C" void kernel_launch(void* const* d_in, const int* in_sizes, int n_in,
                              void* d_out, int out_size) {
    // 1 gather kernel + 1 memcpy node (vs 12 memcpy nodes before)
    setup_kernel<<<1, 320>>>(
        (const float*)d_in[1],  (const float*)d_in[2],  (const float*)d_in[3],
        (const float*)d_in[4],  (const float*)d_in[5],  (const float*)d_in[6],
        (const float*)d_in[7],
        (const float*)d_in[9],  (const float*)d_in[10], (const float*)d_in[11],
        (const float*)d_in[12]);

    void* stage_ptr = nullptr;
    cudaGetSymbolAddress(&stage_ptr, gStage);
    cudaMemcpyToSymbolAsync(cW2, stage_ptr, NW * sizeof(u64), 0,
                            cudaMemcpyDeviceToDevice, 0);

    int B2 = in_sizes[0] / 16;   // rows / 2
    step2_kernel<<<(B2 + 127) / 128, 128>>>((const float4*)d_in[0], (float4*)d_out, B2);
}

// round 3
// speedup vs baseline: 1.3388x; 1.3388x over previous
#include <cuda_runtime.h>

#define FEPS 1e-12f

// ---------- MUFU helpers ----------
__device__ __forceinline__ float ex2a(float x) { float r; asm("ex2.approx.f32 %0, %1;"   : "=f"(r) : "f"(x)); return r; }
__device__ __forceinline__ float rcpa(float x) { float r; asm("rcp.approx.f32 %0, %1;"   : "=f"(r) : "f"(x)); return r; }
__device__ __forceinline__ float rsqa(float x) { float r; asm("rsqrt.approx.f32 %0, %1;" : "=f"(r) : "f"(x)); return r; }
__device__ __forceinline__ float sina(float x) { float r; asm("sin.approx.f32 %0, %1;"   : "=f"(r) : "f"(x)); return r; }
__device__ __forceinline__ float cosa(float x) { float r; asm("cos.approx.f32 %0, %1;"   : "=f"(r) : "f"(x)); return r; }
__device__ __forceinline__ float frcp(float x) {            // rcp.approx + 1 NR step: ~1 ulp-ish
    float r = rcpa(x); return r * (2.0f - x * r);
}
// tanh(x) = 1 - 2/(exp(2x)+1); exp via ex2
#define TWO_LOG2E 2.8853900817779268f
__device__ __forceinline__ float ftanh(float x) {
    float r = rcpa(ex2a(x * TWO_LOG2E) + 1.0f);
    return fmaf(r, -2.0f, 1.0f);
}

// ---------- constant bank: float4-padded layout (79 float4 = 316 floats) ----------
// f4 idx:  0.. 9 Jw1 rows | 10..19 Vw1 rows | 20..29 Vg rows (4*Vw2[k]*Vw1[k][j])
//         30..39 gw1 rows | 40..42 Jb1(pad12) | 43..45 gb1(pad12) | 46..48 Vb1(pad12)
//         49..66 Jw2 (6 rows x 12 pad) | 67..75 gw2 (3 rows x 12 pad)
//         76 gb2(pad4) | 77..78 Jb2(pad8)
__constant__ float4 cK[79];
__device__   float4 gS[79];

__global__ void setup_kernel(const float* Jw1, const float* Jb1, const float* Jw2, const float* Jb2,
                             const float* Vw1, const float* Vb1, const float* Vw2,
                             const float* gw1, const float* gb1, const float* gw2, const float* gb2) {
    int i = threadIdx.x;
    if (i >= 316) return;
    float v = 0.0f;
    if      (i < 40)  v = Jw1[i];
    else if (i < 80)  v = Vw1[i - 40];
    else if (i < 120) { int t = i - 80; v = 4.0f * Vw2[t >> 2] * Vw1[t]; }
    else if (i < 160) v = gw1[i - 120];
    else if (i < 172) { int j = i - 160; v = (j < 10) ? Jb1[j] : 0.0f; }
    else if (i < 184) { int j = i - 172; v = (j < 10) ? gb1[j] : 0.0f; }
    else if (i < 196) { int j = i - 184; v = (j < 10) ? Vb1[j] : 0.0f; }
    else if (i < 268) { int t = i - 196; int r = t / 12, c = t % 12; v = (c < 10) ? Jw2[r * 10 + c] : 0.0f; }
    else if (i < 304) { int t = i - 268; int r = t / 12, c = t % 12; v = (c < 10) ? gw2[r * 10 + c] : 0.0f; }
    else if (i < 308) { int j = i - 304; v = (j < 3) ? gb2[j] : 0.0f; }
    else              { int j = i - 308; v = (j < 6) ? Jb2[j] : 0.0f; }
    ((float*)gS)[i] = v;
}

// dot of float4 row with q + bias, fused
__device__ __forceinline__ float dot4b(float4 w, float q0, float q1, float q2, float q3, float b) {
    return fmaf(w.x, q0, fmaf(w.y, q1, fmaf(w.z, q2, fmaf(w.w, q3, b))));
}
// dot of padded-12 row (3 float4) with hd[10] + bias
__device__ __forceinline__ float dot10b(float4 a, float4 b4, float4 c, const float* h, float b) {
    float s = b;
    s = fmaf(a.x,  h[0], s); s = fmaf(a.y,  h[1], s); s = fmaf(a.z, h[2], s); s = fmaf(a.w, h[3], s);
    s = fmaf(b4.x, h[4], s); s = fmaf(b4.y, h[5], s); s = fmaf(b4.z, h[6], s); s = fmaf(b4.w, h[7], s);
    s = fmaf(c.x,  h[8], s); s = fmaf(c.y,  h[9], s);
    return s;
}

// dV/dq of the V-MLP using folded Vg: d_j = sum_k Vg[k][j] * r_k(1-r_k)
__device__ __forceinline__ void vgrad(float q0, float q1, float q2, float q3,
                                      const float* vb,
                                      float& d0, float& d1, float& d2, float& d3) {
    d0 = d1 = d2 = d3 = 0.0f;
#pragma unroll
    for (int k = 0; k < 10; k++) {
        float4 w = cK[10 + k];
        float z = dot4b(w, q0, q1, q2, q3, vb[k]);
        float r = rcpa(ex2a(z * TWO_LOG2E) + 1.0f);
        float S = fmaf(-r, r, r);                 // r(1-r) = (1-t^2)/4
        float4 g = cK[20 + k];
        d0 = fmaf(g.x, S, d0); d1 = fmaf(g.y, S, d1);
        d2 = fmaf(g.z, S, d2); d3 = fmaf(g.w, S, d3);
    }
}

__global__ void __launch_bounds__(256)
step_kernel(const float4* __restrict__ xin, float4* __restrict__ xout, int B) {
    int i = blockIdx.x * 256 + threadIdx.x;
    if (i >= B) return;

    float4 a = xin[2*i];
    float4 b = xin[2*i + 1];
    float q0 = a.x, q1 = a.y, q2 = a.z, q3 = a.w;
    float w0 = b.x, w1 = b.y, w2 = b.z, u = b.w;

    // bias banks into registers (static-indexed arrays, fully unrolled)
    float4 JB0 = cK[40], JB1 = cK[41], JB2_ = cK[42];
    float jb1[10] = {JB0.x, JB0.y, JB0.z, JB0.w, JB1.x, JB1.y, JB1.z, JB1.w, JB2_.x, JB2_.y};
    float4 GB0 = cK[43], GB1 = cK[44], GB2_ = cK[45];
    float gb1[10] = {GB0.x, GB0.y, GB0.z, GB0.w, GB1.x, GB1.y, GB1.z, GB1.w, GB2_.x, GB2_.y};
    float4 VB0 = cK[46], VB1 = cK[47], VB2_ = cK[48];
    float vb1[10] = {VB0.x, VB0.y, VB0.z, VB0.w, VB1.x, VB1.y, VB1.z, VB1.w, VB2_.x, VB2_.y};
    float4 J2B0 = cK[77], J2B1 = cK[78];
    float jb2[6] = {J2B0.x, J2B0.y, J2B0.z, J2B0.w, J2B1.x, J2B1.y};
    float4 G2B = cK[76];

    // ---- J MLP -> l[6] ----
    float hd[10];
#pragma unroll
    for (int k = 0; k < 10; k++)
        hd[k] = ftanh(dot4b(cK[k], q0, q1, q2, q3, jb1[k]));
    float l[6];
#pragma unroll
    for (int r6 = 0; r6 < 6; r6++)
        l[r6] = dot10b(cK[49 + 3*r6], cK[50 + 3*r6], cK[51 + 3*r6], hd, jb2[r6]);

    // ---- M = L L^T + 0.01 I ----
    float M00 = fmaf(l[0], l[0], 0.01f);
    float M01 = l[0]*l[1];
    float M02 = l[0]*l[3];
    float M11 = fmaf(l[2], l[2], fmaf(l[1], l[1], 0.01f));
    float M12 = fmaf(l[2], l[4], l[1]*l[3]);
    float M22 = fmaf(l[5], l[5], fmaf(l[4], l[4], fmaf(l[3], l[3], 0.01f)));

    // ---- J = inv(M) via adjugate + refined rcp ----
    float c00 = M11*M22 - M12*M12;
    float c01 = M02*M12 - M01*M22;
    float c02 = M01*M12 - M02*M11;
    float c11 = M00*M22 - M02*M02;
    float c12 = M01*M02 - M00*M12;
    float c22 = M00*M11 - M01*M01;
    float det = fmaf(M02, c02, fmaf(M01, c01, M00*c00));
    float id  = frcp(det);
    float J00 = c00*id, J01 = c01*id, J02 = c02*id;
    float J11 = c11*id, J12 = c12*id, J22 = c22*id;

    // ---- g MLP -> fk ----
    float fk0, fk1, fk2;
    {
        float hg[10];
#pragma unroll
        for (int k = 0; k < 10; k++)
            hg[k] = ftanh(dot4b(cK[30 + k], q0, q1, q2, q3, gb1[k]));
        float g0 = dot10b(cK[67], cK[68], cK[69], hg, G2B.x);
        float g1 = dot10b(cK[70], cK[71], cK[72], hg, G2B.y);
        float g2 = dot10b(cK[73], cK[74], cK[75], hg, G2B.z);
        float cu = 0.005f * u;
        fk0 = cu*g0; fk1 = cu*g1; fk2 = cu*g2;
    }

    // ---- pk = 2 J w ----
    float pk0 = 2.0f*fmaf(J02, w2, fmaf(J01, w1, J00*w0));
    float pk1 = 2.0f*fmaf(J12, w2, fmaf(J11, w1, J01*w0));
    float pk2 = 2.0f*fmaf(J22, w2, fmaf(J12, w1, J02*w0));

    // ---- dV at qk, Hd = H(qk) dV ----
    float dv0, dv1, dv2, dv3;
    vgrad(q0, q1, q2, q3, vb1, dv0, dv1, dv2, dv3);
    float Hd0 = fmaf(q1, dv0, fmaf(q0, dv1, q3*dv2 - q2*dv3));
    float Hd1 = fmaf(q2, dv0, fmaf(q0, dv2, q1*dv3 - q3*dv1));
    float Hd2 = fmaf(q3, dv0, fmaf(q0, dv3, q2*dv1 - q1*dv2));

    // ---- NR = -RHS = h/4 * (pk + fk - h/2 Hd) ----
    float NR0 = 0.0025f * fmaf(-0.005f, Hd0, pk0 + fk0);
    float NR1 = 0.0025f * fmaf(-0.005f, Hd1, pk1 + fk1);
    float NR2 = 0.0025f * fmaf(-0.005f, Hd2, pk2 + fk2);

    // ---- Newton iteration 1 (xi=0): jac = -J exactly, update = M * NR ----
    float xi0 = fmaf(M02, NR2, fmaf(M01, NR1, M00*NR0));
    float xi1 = fmaf(M12, NR2, fmaf(M11, NR1, M01*NR0));
    float xi2 = fmaf(M22, NR2, fmaf(M12, NR1, M02*NR0));

    // ---- Newton iterations 2..4 (full, restructured) ----
#pragma unroll
    for (int it = 0; it < 3; it++) {
        float s2v = fmaf(xi2, xi2, fmaf(xi1, xi1, xi0*xi0));
        float scl = fmaxf(s2v, FEPS);
        float rs  = rsqa(scl);
        float th  = scl * rs;
        float sn  = sina(th), cs = cosa(th);
        float si  = sn * rs;                          // sinc
        float gsv = (s2v >= FEPS) ? rs : 0.0f;        // d theta/d xi scale (EPS gate)
        float bsv = (cs - si) * rs * gsv;
        float dsv = -sn * gsv;
        float a1  = -cs * si;
        float ns2 = -si * si;
        float al  = dsv * (-si) - cs * bsv;
        float ga  = -2.0f * si * bsv;

        float Jx0 = fmaf(J02, xi2, fmaf(J01, xi1, J00*xi0));
        float Jx1 = fmaf(J12, xi2, fmaf(J11, xi1, J01*xi0));
        float Jx2 = fmaf(J22, xi2, fmaf(J12, xi1, J02*xi0));
        float cx0 = xi1*Jx2 - xi2*Jx1;
        float cx1 = xi2*Jx0 - xi0*Jx2;
        float cx2 = xi0*Jx1 - xi1*Jx0;

        float r0 = fmaf(a1, Jx0, fmaf(ns2, cx0, NR0));
        float r1 = fmaf(a1, Jx1, fmaf(ns2, cx1, NR1));
        float r2 = fmaf(a1, Jx2, fmaf(ns2, cx2, NR2));

        float w30 = fmaf(ga, cx0, al*Jx0);
        float w31 = fmaf(ga, cx1, al*Jx1);
        float w32 = fmaf(ga, cx2, al*Jx2);

        float xJ00 = xi1*J02 - xi2*J01;
        float xJ01 = xi2*J00 - xi0*J02;
        float xJ02 = xi0*J01 - xi1*J00;
        float xJ10 = xi1*J12 - xi2*J11;
        float xJ11 = xi2*J01 - xi0*J12;
        float xJ12 = xi0*J11 - xi1*J01;
        float xJ20 = xi1*J22 - xi2*J12;
        float xJ21 = xi2*J02 - xi0*J22;
        float xJ22 = xi0*J12 - xi1*J02;
        float T00 = xJ00;       float T01 = xJ01 - Jx2; float T02 = xJ02 + Jx1;
        float T10 = xJ10 + Jx2; float T11 = xJ11;       float T12 = xJ12 - Jx0;
        float T20 = xJ20 - Jx1; float T21 = xJ21 + Jx0; float T22 = xJ22;

        float A00 = fmaf(xi0, w30, fmaf(a1, J00, ns2*T00));
        float A10 = fmaf(xi0, w31, fmaf(a1, J01, ns2*T01));
        float A20 = fmaf(xi0, w32, fmaf(a1, J02, ns2*T02));
        float A01 = fmaf(xi1, w30, fmaf(a1, J01, ns2*T10));
        float A11 = fmaf(xi1, w31, fmaf(a1, J11, ns2*T11));
        float A21 = fmaf(xi1, w32, fmaf(a1, J12, ns2*T12));
        float A02 = fmaf(xi2, w30, fmaf(a1, J02, ns2*T20));
        float A12 = fmaf(xi2, w31, fmaf(a1, J12, ns2*T21));
        float A22 = fmaf(xi2, w32, fmaf(a1, J22, ns2*T22));

        // Cramer solve A d = r
        float cvt0 = A11*A22 - A21*A12;
        float cvt1 = A21*A02 - A01*A22;
        float cvt2 = A01*A12 - A11*A02;
        float ctu0 = A12*A20 - A22*A10;
        float ctu1 = A22*A00 - A02*A20;
        float ctu2 = A02*A10 - A12*A00;
        float cuv0 = A10*A21 - A20*A11;
        float cuv1 = A20*A01 - A00*A21;
        float cuv2 = A00*A11 - A10*A01;
        float dt  = fmaf(A20, cvt2, fmaf(A10, cvt1, A00*cvt0));
        float nid = -frcp(dt);
        float n0 = fmaf(r2, cvt2, fmaf(r1, cvt1, r0*cvt0));
        float n1 = fmaf(r2, ctu2, fmaf(r1, ctu1, r0*ctu0));
        float n2 = fmaf(r2, cuv2, fmaf(r1, cuv1, r0*cuv0));
        xi0 = fmaf(n0, nid, xi0);
        xi1 = fmaf(n1, nid, xi1);
        xi2 = fmaf(n2, nid, xi2);
    }

    // ---- e = quat_exp(xi) ----
    float s2 = fmaf(xi2, xi2, fmaf(xi1, xi1, xi0*xi0));
    float scl = fmaxf(s2, FEPS);
    float rs  = rsqa(scl);
    float th  = scl * rs;
    float e0  = cosa(th);
    float sc  = sina(th) * rs;
    float e1 = xi0*sc, e2 = xi1*sc, e3 = xi2*sc;

    // ---- qn = quat_mul(qk, e) ----
    float qn0 = q0*e0 - fmaf(q3, e3, fmaf(q2, e2, q1*e1));
    float qn1 = fmaf(q0, e1, fmaf(q1, e0, q2*e3 - q3*e2));
    float qn2 = fmaf(q0, e2, fmaf(q2, e0, q3*e1 - q1*e3));
    float qn3 = fmaf(q0, e3, fmaf(q3, e0, q1*e2 - q2*e1));

    // ---- dV at qn ----
    float dn0, dn1, dn2, dn3;
    vgrad(qn0, qn1, qn2, qn3, vb1, dn0, dn1, dn2, dn3);

    // ---- qq = quat_mul(conj(qk), qn) ----
    float qq0 = fmaf(q3, qn3, fmaf(q2, qn2, fmaf(q1, qn1, q0*qn0)));
    float qq1 = fmaf(q0, qn1, (q3*qn2 - q1*qn0) - q2*qn3);
    float qq2 = fmaf(q0, qn2, (q1*qn3 - q2*qn0) - q3*qn1);
    float qq3 = fmaf(q0, qn3, (q2*qn1 - q1*qn2) - q3*qn0);

    // ---- y = J qq_v ; G = qq0*y - qq_v x y ----
    float y0 = fmaf(J02, qq3, fmaf(J01, qq2, J00*qq1));
    float y1 = fmaf(J12, qq3, fmaf(J11, qq2, J01*qq1));
    float y2 = fmaf(J22, qq3, fmaf(J12, qq2, J02*qq1));
    float G0 = fmaf(qq0, y0, qq3*y1 - qq2*y2);
    float G1 = fmaf(qq0, y1, qq1*y2 - qq3*y0);
    float G2 = fmaf(qq0, y2, qq2*y0 - qq1*y1);

    // ---- Hn = H(qn) dn ----
    float Hn0 = fmaf(qn1, dn0, fmaf(qn0, dn1, qn3*dn2 - qn2*dn3));
    float Hn1 = fmaf(qn2, dn0, fmaf(qn0, dn2, qn1*dn3 - qn3*dn1));
    float Hn2 = fmaf(qn3, dn0, fmaf(qn0, dn3, qn2*dn1 - qn1*dn2));

    // ---- pn = 400 G - 0.005 Hn + fk ; wn = 0.5 M pn ----
    float pn0 = fmaf(400.0f, G0, fmaf(-0.005f, Hn0, fk0));
    float pn1 = fmaf(400.0f, G1, fmaf(-0.005f, Hn1, fk1));
    float pn2 = fmaf(400.0f, G2, fmaf(-0.005f, Hn2, fk2));
    float wn0 = 0.5f*fmaf(M02, pn2, fmaf(M01, pn1, M00*pn0));
    float wn1 = 0.5f*fmaf(M12, pn2, fmaf(M11, pn1, M01*pn0));
    float wn2 = 0.5f*fmaf(M22, pn2, fmaf(M12, pn1, M02*pn0));

    xout[2*i]     = make_float4(qn0, qn1, qn2, qn3);
    xout[2*i + 1] = make_float4(wn0, wn1, wn2, u);
}

extern "C" void kernel_launch(void* const* d_in, const int* in_sizes, int n_in,
                              void* d_out, int out_size) {
    setup_kernel<<<1, 320>>>(
        (const float*)d_in[1],  (const float*)d_in[2],  (const float*)d_in[3],
        (const float*)d_in[4],  (const float*)d_in[5],  (const float*)d_in[6],
        (const float*)d_in[7],
        (const float*)d_in[9],  (const float*)d_in[10], (const float*)d_in[11],
        (const float*)d_in[12]);

    void* stage_ptr = nullptr;
    cudaGetSymbolAddress(&stage_ptr, gS);
    cudaMemcpyToSymbolAsync(cK, stage_ptr, 79 * sizeof(float4), 0,
                            cudaMemcpyDeviceToDevice, 0);

    int B = in_sizes[0] / 8;
    step_kernel<<<(B + 255) / 256, 256>>>((const float4*)d_in[0], (float4*)d_out, B);
}

// round 6
// speedup vs baseline: 1.3830x; 1.0330x over previous
#include <cuda_runtime.h>

// ---------- MUFU helpers ----------
__device__ __forceinline__ float ex2a(float x) { float r; asm("ex2.approx.f32 %0, %1;" : "=f"(r) : "f"(x)); return r; }
__device__ __forceinline__ float rcpa(float x) { float r; asm("rcp.approx.f32 %0, %1;" : "=f"(r) : "f"(x)); return r; }
__device__ __forceinline__ float frcp(float x) {            // rcp.approx + 1 NR step
    float r = rcpa(x); return r * (2.0f - x * r);
}
#define TWO_LOG2E 2.8853900817779268f

// tanh with pre-scaled argument zs = 2*log2(e)*z:  tanh = 1 - 2/(2^zs + 1)
__device__ __forceinline__ float ftanh_s(float zs) {
    float r = rcpa(ex2a(zs) + 1.0f);
    return fmaf(r, -2.0f, 1.0f);
}

// ---------- constant bank: float4-padded layout (79 float4 = 316 floats) ----------
// f4 idx:  0.. 9 Jw1*c rows | 10..19 Vw1*c rows | 20..29 Vg rows (4*Vw2[k]*Vw1[k][j], UNscaled)
//         30..39 gw1*c rows | 40..42 Jb1*c(pad12) | 43..45 gb1*c(pad12) | 46..48 Vb1*c(pad12)
//         49..66 Jw2 (6 rows x 12 pad) | 67..75 gw2 (3 rows x 12 pad)
//         76 gb2(pad4) | 77..78 Jb2(pad8)           (c = 2*log2(e), folded for ex2-based tanh)
__constant__ float4 cK[79];
__device__   float4 gS[79];

__global__ void setup_kernel(const float* Jw1, const float* Jb1, const float* Jw2, const float* Jb2,
                             const float* Vw1, const float* Vb1, const float* Vw2,
                             const float* gw1, const float* gb1, const float* gw2, const float* gb2) {
    int i = threadIdx.x;
    if (i >= 316) return;
    float v = 0.0f;
    if      (i < 40)  v = TWO_LOG2E * Jw1[i];
    else if (i < 80)  v = TWO_LOG2E * Vw1[i - 40];
    else if (i < 120) { int t = i - 80; v = 4.0f * Vw2[t >> 2] * Vw1[t]; }
    else if (i < 160) v = TWO_LOG2E * gw1[i - 120];
    else if (i < 172) { int j = i - 160; v = (j < 10) ? TWO_LOG2E * Jb1[j] : 0.0f; }
    else if (i < 184) { int j = i - 172; v = (j < 10) ? TWO_LOG2E * gb1[j] : 0.0f; }
    else if (i < 196) { int j = i - 184; v = (j < 10) ? TWO_LOG2E * Vb1[j] : 0.0f; }
    else if (i < 268) { int t = i - 196; int r = t / 12, c = t % 12; v = (c < 10) ? Jw2[r * 10 + c] : 0.0f; }
    else if (i < 304) { int t = i - 268; int r = t / 12, c = t % 12; v = (c < 10) ? gw2[r * 10 + c] : 0.0f; }
    else if (i < 308) { int j = i - 304; v = (j < 3) ? gb2[j] : 0.0f; }
    else              { int j = i - 308; v = (j < 6) ? Jb2[j] : 0.0f; }
    ((float*)gS)[i] = v;
}

__device__ __forceinline__ float dot4b(float4 w, float q0, float q1, float q2, float q3, float b) {
    return fmaf(w.x, q0, fmaf(w.y, q1, fmaf(w.z, q2, fmaf(w.w, q3, b))));
}
__device__ __forceinline__ float dot10b(float4 a, float4 b4, float4 c, const float* h, float b) {
    float s = b;
    s = fmaf(a.x,  h[0], s); s = fmaf(a.y,  h[1], s); s = fmaf(a.z, h[2], s); s = fmaf(a.w, h[3], s);
    s = fmaf(b4.x, h[4], s); s = fmaf(b4.y, h[5], s); s = fmaf(b4.z, h[6], s); s = fmaf(b4.w, h[7], s);
    s = fmaf(c.x,  h[8], s); s = fmaf(c.y,  h[9], s);
    return s;
}

// dV/dq: d_j = sum_k Vg[k][j] * r_k(1-r_k), r_k = 1/(2^(zs_k)+1), zs pre-scaled
__device__ __forceinline__ void vgrad(float q0, float q1, float q2, float q3,
                                      const float* vb,
                                      float& d0, float& d1, float& d2, float& d3) {
    d0 = d1 = d2 = d3 = 0.0f;
#pragma unroll
    for (int k = 0; k < 10; k++) {
        float zs = dot4b(cK[10 + k], q0, q1, q2, q3, vb[k]);
        float r = rcpa(ex2a(zs) + 1.0f);
        float S = fmaf(-r, r, r);                 // r(1-r) = (1-tanh^2)/4
        float4 g = cK[20 + k];
        d0 = fmaf(g.x, S, d0); d1 = fmaf(g.y, S, d1);
        d2 = fmaf(g.z, S, d2); d3 = fmaf(g.w, S, d3);
    }
}

// polynomials in s = theta^2 (s <= ~2e-4 here; truncation ~1e-16)
__device__ __forceinline__ float polyC(float s) {   // cos(sqrt(s))
    return fmaf(s, fmaf(s, fmaf(s, -1.0f/720.0f,  1.0f/24.0f),  -0.5f),      1.0f);
}
__device__ __forceinline__ float polyS(float s) {   // sinc(sqrt(s))
    return fmaf(s, fmaf(s, fmaf(s, -1.0f/5040.0f, 1.0f/120.0f), -1.0f/6.0f), 1.0f);
}
__device__ __forceinline__ float polySp(float s) {  // d sinc / d s
    return fmaf(s, fmaf(s, -1.0f/1680.0f, 1.0f/60.0f), -1.0f/6.0f);
}

__global__ void __launch_bounds__(256)
step_kernel(const float4* __restrict__ xin, float4* __restrict__ xout, int B) {
    int i = blockIdx.x * 256 + threadIdx.x;
    if (i >= B) return;

    float4 a = xin[2*i];
    float4 b = xin[2*i + 1];
    float q0 = a.x, q1 = a.y, q2 = a.z, q3 = a.w;
    float w0 = b.x, w1 = b.y, w2 = b.z, u = b.w;

    float4 JB0 = cK[40], JB1 = cK[41], JB2_ = cK[42];
    float jb1[10] = {JB0.x, JB0.y, JB0.z, JB0.w, JB1.x, JB1.y, JB1.z, JB1.w, JB2_.x, JB2_.y};
    float4 GB0 = cK[43], GB1 = cK[44], GB2_ = cK[45];
    float gb1[10] = {GB0.x, GB0.y, GB0.z, GB0.w, GB1.x, GB1.y, GB1.z, GB1.w, GB2_.x, GB2_.y};
    float4 VB0 = cK[46], VB1 = cK[47], VB2_ = cK[48];
    float vb1[10] = {VB0.x, VB0.y, VB0.z, VB0.w, VB1.x, VB1.y, VB1.z, VB1.w, VB2_.x, VB2_.y};
    float4 J2B0 = cK[77], J2B1 = cK[78];
    float jb2[6] = {J2B0.x, J2B0.y, J2B0.z, J2B0.w, J2B1.x, J2B1.y};
    float4 G2B = cK[76];

    // ---- J MLP -> l[6] ----
    float hd[10];
#pragma unroll
    for (int k = 0; k < 10; k++)
        hd[k] = ftanh_s(dot4b(cK[k], q0, q1, q2, q3, jb1[k]));
    float l[6];
#pragma unroll
    for (int r6 = 0; r6 < 6; r6++)
        l[r6] = dot10b(cK[49 + 3*r6], cK[50 + 3*r6], cK[51 + 3*r6], hd, jb2[r6]);

    // ---- M = L L^T + 0.01 I ----
    float M00 = fmaf(l[0], l[0], 0.01f);
    float M01 = l[0]*l[1];
    float M02 = l[0]*l[3];
    float M11 = fmaf(l[2], l[2], fmaf(l[1], l[1], 0.01f));
    float M12 = fmaf(l[2], l[4], l[1]*l[3]);
    float M22 = fmaf(l[5], l[5], fmaf(l[4], l[4], fmaf(l[3], l[3], 0.01f)));

    // ---- J = inv(M) via adjugate + refined rcp ----
    float c00 = M11*M22 - M12*M12;
    float c01 = M02*M12 - M01*M22;
    float c02 = M01*M12 - M02*M11;
    float c11 = M00*M22 - M02*M02;
    float c12 = M01*M02 - M00*M12;
    float c22 = M00*M11 - M01*M01;
    float det = fmaf(M02, c02, fmaf(M01, c01, M00*c00));
    float id  = frcp(det);
    float J00 = c00*id, J01 = c01*id, J02 = c02*id;
    float J11 = c11*id, J12 = c12*id, J22 = c22*id;

    // ---- g MLP -> fk ----
    float fk0, fk1, fk2;
    {
        float hg[10];
#pragma unroll
        for (int k = 0; k < 10; k++)
            hg[k] = ftanh_s(dot4b(cK[30 + k], q0, q1, q2, q3, gb1[k]));
        float g0 = dot10b(cK[67], cK[68], cK[69], hg, G2B.x);
        float g1 = dot10b(cK[70], cK[71], cK[72], hg, G2B.y);
        float g2 = dot10b(cK[73], cK[74], cK[75], hg, G2B.z);
        float cu = 0.005f * u;
        fk0 = cu*g0; fk1 = cu*g1; fk2 = cu*g2;
    }

    // ---- pk = 2 J w ----
    float pk0 = 2.0f*fmaf(J02, w2, fmaf(J01, w1, J00*w0));
    float pk1 = 2.0f*fmaf(J12, w2, fmaf(J11, w1, J01*w0));
    float pk2 = 2.0f*fmaf(J22, w2, fmaf(J12, w1, J02*w0));

    // ---- dV at qk, Hd = H(qk) dV ----
    float dv0, dv1, dv2, dv3;
    vgrad(q0, q1, q2, q3, vb1, dv0, dv1, dv2, dv3);
    float Hd0 = fmaf(q1, dv0, fmaf(q0, dv1, q3*dv2 - q2*dv3));
    float Hd1 = fmaf(q2, dv0, fmaf(q0, dv2, q1*dv3 - q3*dv1));
    float Hd2 = fmaf(q3, dv0, fmaf(q0, dv3, q2*dv1 - q1*dv2));

    // ---- NR = -RHS = h/4 * (pk + fk - h/2 Hd) ----
    float NR0 = 0.0025f * fmaf(-0.005f, Hd0, pk0 + fk0);
    float NR1 = 0.0025f * fmaf(-0.005f, Hd1, pk1 + fk1);
    float NR2 = 0.0025f * fmaf(-0.005f, Hd2, pk2 + fk2);

    // ---- Newton step 1 (xi=0 exact): jac(0) = -J, jac(0)^-1 = -M  =>  xi1 = M*NR ----
    float xi0 = fmaf(M02, NR2, fmaf(M01, NR1, M00*NR0));
    float xi1 = fmaf(M12, NR2, fmaf(M11, NR1, M01*NR0));
    float xi2 = fmaf(M22, NR2, fmaf(M12, NR1, M02*NR0));

    // ---- Newton steps 2..4: FULL exact Jacobian (R3-proven), poly trig in s ----
    // a1 = -C*S, ns2 = -S^2, al = S^2 - 2*C*Sp, ga = -4*S*Sp  (== gated form for s>=EPS;
    // for s<EPS the difference enters jac at ~1e-12 relative -> negligible)
#pragma unroll
    for (int it = 0; it < 3; it++) {
        float s2v = fmaf(xi2, xi2, fmaf(xi1, xi1, xi0*xi0));
        float cs = polyC(s2v);
        float si = polyS(s2v);
        float Sp = polySp(s2v);
        float a1  = -cs*si;
        float ns2 = -si*si;
        float al  = fmaf(si, si, -2.0f*cs*Sp);
        float ga  = -4.0f*si*Sp;

        float Jx0 = fmaf(J02, xi2, fmaf(J01, xi1, J00*xi0));
        float Jx1 = fmaf(J12, xi2, fmaf(J11, xi1, J01*xi0));
        float Jx2 = fmaf(J22, xi2, fmaf(J12, xi1, J02*xi0));
        float cx0 = xi1*Jx2 - xi2*Jx1;
        float cx1 = xi2*Jx0 - xi0*Jx2;
        float cx2 = xi0*Jx1 - xi1*Jx0;

        float r0 = fmaf(a1, Jx0, fmaf(ns2, cx0, NR0));
        float r1 = fmaf(a1, Jx1, fmaf(ns2, cx1, NR1));
        float r2 = fmaf(a1, Jx2, fmaf(ns2, cx2, NR2));

        float w30 = fmaf(ga, cx0, al*Jx0);
        float w31 = fmaf(ga, cx1, al*Jx1);
        float w32 = fmaf(ga, cx2, al*Jx2);

        float xJ00 = xi1*J02 - xi2*J01;
        float xJ01 = xi2*J00 - xi0*J02;
        float xJ02 = xi0*J01 - xi1*J00;
        float xJ10 = xi1*J12 - xi2*J11;
        float xJ11 = xi2*J01 - xi0*J12;
        float xJ12 = xi0*J11 - xi1*J01;
        float xJ20 = xi1*J22 - xi2*J12;
        float xJ21 = xi2*J02 - xi0*J22;
        float xJ22 = xi0*J12 - xi1*J02;
        float T00 = xJ00;       float T01 = xJ01 - Jx2; float T02 = xJ02 + Jx1;
        float T10 = xJ10 + Jx2; float T11 = xJ11;       float T12 = xJ12 - Jx0;
        float T20 = xJ20 - Jx1; float T21 = xJ21 + Jx0; float T22 = xJ22;

        float A00 = fmaf(xi0, w30, fmaf(a1, J00, ns2*T00));
        float A10 = fmaf(xi0, w31, fmaf(a1, J01, ns2*T01));
        float A20 = fmaf(xi0, w32, fmaf(a1, J02, ns2*T02));
        float A01 = fmaf(xi1, w30, fmaf(a1, J01, ns2*T10));
        float A11 = fmaf(xi1, w31, fmaf(a1, J11, ns2*T11));
        float A21 = fmaf(xi1, w32, fmaf(a1, J12, ns2*T12));
        float A02 = fmaf(xi2, w30, fmaf(a1, J02, ns2*T20));
        float A12 = fmaf(xi2, w31, fmaf(a1, J12, ns2*T21));
        float A22 = fmaf(xi2, w32, fmaf(a1, J22, ns2*T22));

        // Cramer solve A d = r
        float cvt0 = A11*A22 - A21*A12;
        float cvt1 = A21*A02 - A01*A22;
        float cvt2 = A01*A12 - A11*A02;
        float ctu0 = A12*A20 - A22*A10;
        float ctu1 = A22*A00 - A02*A20;
        float ctu2 = A02*A10 - A12*A00;
        float cuv0 = A10*A21 - A20*A11;
        float cuv1 = A20*A01 - A00*A21;
        float cuv2 = A00*A11 - A10*A01;
        float dt  = fmaf(A20, cvt2, fmaf(A10, cvt1, A00*cvt0));
        float nid = -rcpa(dt);                     // approx rcp: ~1.5e-7 rel -> ~1e-9 on xi
        float n0 = fmaf(r2, cvt2, fmaf(r1, cvt1, r0*cvt0));
        float n1 = fmaf(r2, ctu2, fmaf(r1, ctu1, r0*ctu0));
        float n2 = fmaf(r2, cuv2, fmaf(r1, cuv1, r0*cuv0));
        xi0 = fmaf(n0, nid, xi0);
        xi1 = fmaf(n1, nid, xi1);
        xi2 = fmaf(n2, nid, xi2);
    }

    // ---- e = quat_exp(xi): poly (smooth; EPS clamp moot to <1e-13) ----
    float s  = fmaf(xi2, xi2, fmaf(xi1, xi1, xi0*xi0));
    float e0 = polyC(s);
    float sc = polyS(s);
    float e1 = xi0*sc, e2 = xi1*sc, e3 = xi2*sc;

    // ---- qn = quat_mul(qk, e) ----
    float qn0 = q0*e0 - fmaf(q3, e3, fmaf(q2, e2, q1*e1));
    float qn1 = fmaf(q0, e1, fmaf(q1, e0, q2*e3 - q3*e2));
    float qn2 = fmaf(q0, e2, fmaf(q2, e0, q3*e1 - q1*e3));
    float qn3 = fmaf(q0, e3, fmaf(q3, e0, q1*e2 - q2*e1));

    // ---- dV at qn ----
    float dn0, dn1, dn2, dn3;
    vgrad(qn0, qn1, qn2, qn3, vb1, dn0, dn1, dn2, dn3);

    // ---- qq = quat_mul(conj(qk), qn) ----
    float qq0 = fmaf(q3, qn3, fmaf(q2, qn2, fmaf(q1, qn1, q0*qn0)));
    float qq1 = fmaf(q0, qn1, (q3*qn2 - q1*qn0) - q2*qn3);
    float qq2 = fmaf(q0, qn2, (q1*qn3 - q2*qn0) - q3*qn1);
    float qq3 = fmaf(q0, qn3, (q2*qn1 - q1*qn2) - q3*qn0);

    // ---- y = J qq_v ; G = qq0*y - qq_v x y ----
    float y0 = fmaf(J02, qq3, fmaf(J01, qq2, J00*qq1));
    float y1 = fmaf(J12, qq3, fmaf(J11, qq2, J01*qq1));
    float y2 = fmaf(J22, qq3, fmaf(J12, qq2, J02*qq1));
    float G0 = fmaf(qq0, y0, qq3*y1 - qq2*y2);
    float G1 = fmaf(qq0, y1, qq1*y2 - qq3*y0);
    float G2 = fmaf(qq0, y2, qq2*y0 - qq1*y1);

    // ---- Hn = H(qn) dn ----
    float Hn0 = fmaf(qn1, dn0, fmaf(qn0, dn1, qn3*dn2 - qn2*dn3));
    float Hn1 = fmaf(qn2, dn0, fmaf(qn0, dn2, qn1*dn3 - qn3*dn1));
    float Hn2 = fmaf(qn3, dn0, fmaf(qn0, dn3, qn2*dn1 - qn1*dn2));

    // ---- pn = 400 G - 0.005 Hn + fk ; wn = 0.5 M pn ----
    float pn0 = fmaf(400.0f, G0, fmaf(-0.005f, Hn0, fk0));
    float pn1 = fmaf(400.0f, G1, fmaf(-0.005f, Hn1, fk1));
    float pn2 = fmaf(400.0f, G2, fmaf(-0.005f, Hn2, fk2));
    float wn0 = 0.5f*fmaf(M02, pn2, fmaf(M01, pn1, M00*pn0));
    float wn1 = 0.5f*fmaf(M12, pn2, fmaf(M11, pn1, M01*pn0));
    float wn2 = 0.5f*fmaf(M22, pn2, fmaf(M12, pn1, M02*pn0));

    xout[2*i]     = make_float4(qn0, qn1, qn2, qn3);
    xout[2*i + 1] = make_float4(wn0, wn1, wn2, u);
}

extern "C" void kernel_launch(void* const* d_in, const int* in_sizes, int n_in,
                              void* d_out, int out_size) {
    setup_kernel<<<1, 320>>>(
        (const float*)d_in[1],  (const float*)d_in[2],  (const float*)d_in[3],
        (const float*)d_in[4],  (const float*)d_in[5],  (const float*)d_in[6],
        (const float*)d_in[7],
        (const float*)d_in[9],  (const float*)d_in[10], (const float*)d_in[11],
        (const float*)d_in[12]);

    void* stage_ptr = nullptr;
    cudaGetSymbolAddress(&stage_ptr, gS);
    cudaMemcpyToSymbolAsync(cK, stage_ptr, 79 * sizeof(float4), 0,
                            cudaMemcpyDeviceToDevice, 0);

    int B = in_sizes[0] / 8;
    step_kernel<<<(B + 255) / 256, 256>>>((const float4*)d_in[0], (float4*)d_out, B);
}